// round 3
// baseline (speedup 1.0000x reference)
#include <cuda_runtime.h>

#define H 128
#define MAXN 100000
#define RPW 8
#define WARPS 8
#define TPB 256

// ---------------- scratch (device globals; no allocations anywhere) ----------------
__device__ __align__(128) float g_agg[MAXN * H];
__device__ __align__(128) float g_deg[MAXN];
__device__ __align__(128) float g_x1[MAXN * H];
__device__ __align__(128) float g_u[MAXN * H];
__device__ __align__(128) float g_v[MAXN * H];

// ---------------- f32x2 packed helpers (full-rate fp32 on sm_103a) ----------------
static __device__ __forceinline__ unsigned long long pk2(float a, float b) {
    unsigned long long r;
    asm("mov.b64 %0, {%1,%2};" : "=l"(r) : "f"(a), "f"(b));
    return r;
}
static __device__ __forceinline__ void fma2(unsigned long long& d, unsigned long long a,
                                            unsigned long long b) {
    asm("fma.rn.f32x2 %0, %1, %2, %0;" : "+l"(d) : "l"(a), "l"(b));
}
static __device__ __forceinline__ float2 upk(unsigned long long a) {
    float2 r;
    asm("mov.b64 {%0,%1}, %2;" : "=f"(r.x), "=f"(r.y) : "l"(a));
    return r;
}

// ---------------- zero ----------------
__global__ void zero_kernel(float4* p, int n4) {
    int i = blockIdx.x * blockDim.x + threadIdx.x;
    if (i < n4) p[i] = make_float4(0.f, 0.f, 0.f, 0.f);
}

// ---------------- edge scatter: agg[dst] += x[src], deg[dst] += 1 ----------------
// warp per edge; lane covers 4 floats -> one red.v4 per lane (32 per edge).
// NOTE: indices are int32 (JAX x64 disabled -> "int64" arrays are really int32).
__global__ void scatter_kernel(const float* __restrict__ x, const int* __restrict__ src,
                               const int* __restrict__ dst, float* __restrict__ agg,
                               float* __restrict__ deg, int nE) {
    int lane = threadIdx.x & 31;
    int w = (blockIdx.x * blockDim.x + threadIdx.x) >> 5;
    int nw = (gridDim.x * blockDim.x) >> 5;
    for (int e = w; e < nE; e += nw) {
        size_t s = (size_t)src[e];
        size_t d = (size_t)dst[e];
        float4 val = *(const float4*)(x + s * H + (size_t)lane * 4);
        float* p = agg + d * H + (size_t)lane * 4;
        asm volatile("red.global.add.v4.f32 [%0], {%1,%2,%3,%4};" ::"l"(p), "f"(val.x),
                         "f"(val.y), "f"(val.z), "f"(val.w)
                     : "memory");
        if (deg != nullptr && lane == 0) atomicAdd(deg + d, 1.0f);
    }
}

// ---------------- fused SAGE layer: out = relu((agg/max(deg,1))@Wl + x@Wr + b) ----------------
__global__ void __launch_bounds__(TPB, 1)
layer_kernel(const float* __restrict__ x, const float* __restrict__ agg,
             const float* __restrict__ deg, const float* __restrict__ Wl,
             const float* __restrict__ Wr, const float* __restrict__ bias,
             float* __restrict__ out, int n) {
    extern __shared__ float sm[];
    float* Ws = sm;                 // 256*128 floats
    float* stage = sm + 256 * H;    // WARPS * RPW * 256 floats
    for (int i = threadIdx.x; i < H * H; i += TPB) {
        Ws[i] = Wl[i];
        Ws[H * H + i] = Wr[i];
    }
    __syncthreads();
    const int warp = threadIdx.x >> 5, lane = threadIdx.x & 31;
    const int c0 = lane * 4;
    float* st = stage + warp * (RPW * 256);
    const float4 b4 = *(const float4*)(bias + c0);

    for (int base = blockIdx.x * (WARPS * RPW) + warp * RPW; base < n;
         base += gridDim.x * (WARPS * RPW)) {
#pragma unroll
        for (int r = 0; r < RPW; r++) {
            int row = base + r;
            if (row < n) {
                float rd = 1.0f / fmaxf(deg[row], 1.0f);
                float4 av = *(const float4*)(agg + (size_t)row * H + c0);
                float4 xv = *(const float4*)(x + (size_t)row * H + c0);
                av.x *= rd; av.y *= rd; av.z *= rd; av.w *= rd;
                *(float4*)(st + r * 256 + c0) = av;
                *(float4*)(st + r * 256 + 128 + c0) = xv;
            }
        }
        __syncwarp();

        unsigned long long acc0[RPW], acc1[RPW];
#pragma unroll
        for (int r = 0; r < RPW; r++) { acc0[r] = 0ull; acc1[r] = 0ull; }

#pragma unroll 2
        for (int k4 = 0; k4 < 64; k4++) {
            float4 a4[RPW];
#pragma unroll
            for (int r = 0; r < RPW; r++) a4[r] = *(const float4*)(st + r * 256 + k4 * 4);
#pragma unroll
            for (int j = 0; j < 4; j++) {
                float4 wv = *(const float4*)(Ws + (k4 * 4 + j) * H + c0);
                unsigned long long w01 = pk2(wv.x, wv.y), w23 = pk2(wv.z, wv.w);
#pragma unroll
                for (int r = 0; r < RPW; r++) {
                    float a = (j == 0) ? a4[r].x : (j == 1) ? a4[r].y : (j == 2) ? a4[r].z
                                                                                 : a4[r].w;
                    unsigned long long a2 = pk2(a, a);
                    fma2(acc0[r], w01, a2);
                    fma2(acc1[r], w23, a2);
                }
            }
        }

#pragma unroll
        for (int r = 0; r < RPW; r++) {
            int row = base + r;
            if (row < n) {
                float2 p0 = upk(acc0[r]), p1 = upk(acc1[r]);
                float4 o;
                o.x = fmaxf(p0.x + b4.x, 0.f);
                o.y = fmaxf(p0.y + b4.y, 0.f);
                o.z = fmaxf(p1.x + b4.z, 0.f);
                o.w = fmaxf(p1.y + b4.w, 0.f);
                *(float4*)(out + (size_t)row * H + c0) = o;
            }
        }
        __syncwarp();
    }
}

// ---------------- u/v precompute: u = x@W1[0:128,:], v = x@W1[128:256,:] ----------------
__global__ void __launch_bounds__(TPB, 1)
uv_kernel(const float* __restrict__ x, const float* __restrict__ W1, float* __restrict__ u,
          float* __restrict__ v, int n) {
    extern __shared__ float sm[];
    float* Ws = sm;               // full W1: 256*128 floats
    float* stage = sm + 256 * H;  // WARPS * RPW * 128 floats
    for (int i = threadIdx.x; i < 256 * H; i += TPB) Ws[i] = W1[i];
    __syncthreads();
    const int warp = threadIdx.x >> 5, lane = threadIdx.x & 31;
    const int c0 = lane * 4;
    float* st = stage + warp * (RPW * H);

    for (int base = blockIdx.x * (WARPS * RPW) + warp * RPW; base < n;
         base += gridDim.x * (WARPS * RPW)) {
#pragma unroll
        for (int r = 0; r < RPW; r++) {
            int row = base + r;
            if (row < n) {
                float4 xv = *(const float4*)(x + (size_t)row * H + c0);
                *(float4*)(st + r * H + c0) = xv;
            }
        }
        __syncwarp();

        unsigned long long ua0[RPW], ua1[RPW], va0[RPW], va1[RPW];
#pragma unroll
        for (int r = 0; r < RPW; r++) { ua0[r] = 0ull; ua1[r] = 0ull; va0[r] = 0ull; va1[r] = 0ull; }

        for (int k4 = 0; k4 < 32; k4++) {
            float4 a4[RPW];
#pragma unroll
            for (int r = 0; r < RPW; r++) a4[r] = *(const float4*)(st + r * H + k4 * 4);
#pragma unroll
            for (int j = 0; j < 4; j++) {
                int k = k4 * 4 + j;
                float4 wt = *(const float4*)(Ws + k * H + c0);
                float4 wb = *(const float4*)(Ws + (128 + k) * H + c0);
                unsigned long long wt01 = pk2(wt.x, wt.y), wt23 = pk2(wt.z, wt.w);
                unsigned long long wb01 = pk2(wb.x, wb.y), wb23 = pk2(wb.z, wb.w);
#pragma unroll
                for (int r = 0; r < RPW; r++) {
                    float a = (j == 0) ? a4[r].x : (j == 1) ? a4[r].y : (j == 2) ? a4[r].z
                                                                                 : a4[r].w;
                    unsigned long long a2 = pk2(a, a);
                    fma2(ua0[r], wt01, a2);
                    fma2(ua1[r], wt23, a2);
                    fma2(va0[r], wb01, a2);
                    fma2(va1[r], wb23, a2);
                }
            }
        }

#pragma unroll
        for (int r = 0; r < RPW; r++) {
            int row = base + r;
            if (row < n) {
                float2 p0 = upk(ua0[r]), p1 = upk(ua1[r]);
                float2 q0 = upk(va0[r]), q1 = upk(va1[r]);
                *(float4*)(u + (size_t)row * H + c0) = make_float4(p0.x, p0.y, p1.x, p1.y);
                *(float4*)(v + (size_t)row * H + c0) = make_float4(q0.x, q0.y, q1.x, q1.y);
            }
        }
        __syncwarp();
    }
}

// ---------------- edge classifier: logits = relu(u[s]+v[d]+b1) @ W2 + b2 ----------------
__global__ void edge_kernel(const float* __restrict__ u, const float* __restrict__ v,
                            const int* __restrict__ qs, const int* __restrict__ qd,
                            const float* __restrict__ b1, const float* __restrict__ W2,
                            const float* __restrict__ b2, float* __restrict__ out, int nq) {
    __shared__ float W2s[H * 8];
    __shared__ float b1s[H];
    __shared__ float b2s[8];
    for (int i = threadIdx.x; i < H * 8; i += blockDim.x) W2s[i] = W2[i];
    for (int i = threadIdx.x; i < H; i += blockDim.x) b1s[i] = b1[i];
    if (threadIdx.x < 8) b2s[threadIdx.x] = b2[threadIdx.x];
    __syncthreads();

    int idx = blockIdx.x * blockDim.x + threadIdx.x;
    int stride = gridDim.x * blockDim.x;
    for (int e = idx; e < nq; e += stride) {
        size_t s = (size_t)qs[e];
        size_t d = (size_t)qd[e];
        const float4* ur = (const float4*)(u + s * H);
        const float4* vr = (const float4*)(v + d * H);
        float lg[8];
#pragma unroll
        for (int c = 0; c < 8; c++) lg[c] = b2s[c];
#pragma unroll 8
        for (int k4 = 0; k4 < 32; k4++) {
            float4 a = __ldg(ur + k4);
            float4 b = __ldg(vr + k4);
            float h0 = fmaxf(a.x + b.x + b1s[k4 * 4 + 0], 0.f);
            float h1 = fmaxf(a.y + b.y + b1s[k4 * 4 + 1], 0.f);
            float h2 = fmaxf(a.z + b.z + b1s[k4 * 4 + 2], 0.f);
            float h3 = fmaxf(a.w + b.w + b1s[k4 * 4 + 3], 0.f);
#pragma unroll
            for (int c = 0; c < 8; c++) {
                lg[c] += h0 * W2s[(k4 * 4 + 0) * 8 + c];
                lg[c] += h1 * W2s[(k4 * 4 + 1) * 8 + c];
                lg[c] += h2 * W2s[(k4 * 4 + 2) * 8 + c];
                lg[c] += h3 * W2s[(k4 * 4 + 3) * 8 + c];
            }
        }
        float4* op = (float4*)(out + (size_t)e * 8);
        op[0] = make_float4(lg[0], lg[1], lg[2], lg[3]);
        op[1] = make_float4(lg[4], lg[5], lg[6], lg[7]);
    }
}

// ---------------- host ----------------
#define SMEM_LAYER ((256 * H + WARPS * RPW * 256) * 4)
#define SMEM_UV ((256 * H + WARPS * RPW * 128) * 4)

extern "C" void kernel_launch(void* const* d_in, const int* in_sizes, int n_in, void* d_out,
                              int out_size) {
    const float* node_emb = (const float*)d_in[0];
    const float* Wl0 = (const float*)d_in[1];
    const float* bl0 = (const float*)d_in[2];
    const float* Wr0 = (const float*)d_in[3];
    const float* Wl1 = (const float*)d_in[4];
    const float* bl1 = (const float*)d_in[5];
    const float* Wr1 = (const float*)d_in[6];
    const float* mW1 = (const float*)d_in[7];
    const float* mb1 = (const float*)d_in[8];
    const float* mW2 = (const float*)d_in[9];
    const float* mb2 = (const float*)d_in[10];
    const int* eidx = (const int*)d_in[11];   // int32 (JAX x64 disabled)
    const int* eq = (const int*)d_in[12];     // int32

    const int n = in_sizes[0] / H;      // 100000
    const int nE = in_sizes[11] / 2;    // 1600000
    const int nq = in_sizes[12] / 2;    // 500000

    float *agg, *deg, *x1, *u, *v;
    cudaGetSymbolAddress((void**)&agg, g_agg);
    cudaGetSymbolAddress((void**)&deg, g_deg);
    cudaGetSymbolAddress((void**)&x1, g_x1);
    cudaGetSymbolAddress((void**)&u, g_u);
    cudaGetSymbolAddress((void**)&v, g_v);

    int sms = 148;
    cudaDeviceGetAttribute(&sms, cudaDevAttrMultiProcessorCount, 0);
    cudaFuncSetAttribute(layer_kernel, cudaFuncAttributeMaxDynamicSharedMemorySize, SMEM_LAYER);
    cudaFuncSetAttribute(uv_kernel, cudaFuncAttributeMaxDynamicSharedMemorySize, SMEM_UV);

    const int n4 = n * H / 4;
    const int scatter_blocks = sms * 16;

    // layer 0
    zero_kernel<<<(n4 + 255) / 256, 256>>>((float4*)agg, n4);
    zero_kernel<<<(n / 4 + 255) / 256, 256>>>((float4*)deg, n / 4);
    scatter_kernel<<<scatter_blocks, 256>>>(node_emb, eidx, eidx + nE, agg, deg, nE);
    layer_kernel<<<sms, TPB, SMEM_LAYER>>>(node_emb, agg, deg, Wl0, Wr0, bl0, x1, n);

    // layer 1 (in-place on x1; row-local so safe)
    zero_kernel<<<(n4 + 255) / 256, 256>>>((float4*)agg, n4);
    scatter_kernel<<<scatter_blocks, 256>>>(x1, eidx, eidx + nE, agg, nullptr, nE);
    layer_kernel<<<sms, TPB, SMEM_LAYER>>>(x1, agg, deg, Wl1, Wr1, bl1, x1, n);

    // edge classifier
    uv_kernel<<<sms, TPB, SMEM_UV>>>(x1, mW1, u, v, n);
    edge_kernel<<<(nq + TPB - 1) / TPB, TPB>>>(u, v, eq, eq + nq, mb1, mW2, mb2, (float*)d_out,
                                               nq);
}